// round 7
// baseline (speedup 1.0000x reference)
#include <cuda_runtime.h>
#include <math.h>

// MaskAlignmentLoss: fused single-kernel exact grid-NN search.
// B=4, N=6890, H=W=64. Pixel units; scale 1/64 applied per term.

#define BATCH   4
#define NV      6890
#define HW      4096
#define INF2    1.0e18f
#define INV64   0.015625f
#define BIGF    1.0e9f
#define NB_PIX  64                 // pixel-query blocks (16 per batch); 0..3 also prep
#define NB_VERT 108                // vert-query blocks (27648 >= 27560)
#define NBLK    (NB_PIX + NB_VERT) // 172
#define SMEM_BYTES (4096 * 4 + NV * 8)   // 71504: bin table + sorted verts

// -------- persistent device state (no init required across replays) --------
__device__ unsigned g_binpack[BATCH][4096];        // off | (cnt<<16)
__device__ __align__(16) float2 g_vsort[BATCH][NV];
__device__ float    g_partial[NBLK];
__device__ unsigned g_barrier;     // monotonic, pixel blocks only
__device__ unsigned g_ticket;      // monotonic finish ticket

__device__ __forceinline__ float sqrt_ap(float x) {
    float r; asm("sqrt.approx.f32 %0, %1;" : "=f"(r) : "f"(x)); return r;
}

extern __shared__ __align__(16) unsigned dyn_u[];

__global__ void __launch_bounds__(256) k_fused(const float* __restrict__ vert,
                                               const int*   __restrict__ mask,
                                               float*       __restrict__ out) {
    __shared__ float red[256];
    __shared__ unsigned wtot[8];
    __shared__ int lastflag;

    const int bx = blockIdx.x, tid = threadIdx.x;
    const int lane = tid & 31, wid = tid >> 5;
    float s = 0.0f;

    if (bx < NB_PIX) {
        // ================== prep (blocks 0..3, batch = bx) ==================
        if (bx < BATCH) {
            const int b = bx;
            unsigned* cursor = dyn_u;                       // 4096 words
            for (int i = tid; i < 4096; i += 256) cursor[i] = 0;
            __syncthreads();
            const float2* vb = (const float2*)(vert + (size_t)b * NV * 2);
            for (int i = tid; i < NV; i += 256) {
                float2 v = vb[i];
                int ix = min(63, (int)v.x), iy = min(63, (int)v.y);
                atomicAdd(&cursor[iy * 64 + ix], 1u);
            }
            __syncthreads();
            unsigned c[16], tsum = 0;
#pragma unroll
            for (int k = 0; k < 16; k++) { c[k] = cursor[tid * 16 + k]; tsum += c[k]; }
            unsigned incl = tsum;
#pragma unroll
            for (int d = 1; d < 32; d <<= 1) {
                unsigned t = __shfl_up_sync(0xffffffffu, incl, d);
                if (lane >= d) incl += t;
            }
            if (lane == 31) wtot[wid] = incl;
            __syncthreads();
            unsigned base = incl - tsum;
            for (int w = 0; w < wid; w++) base += wtot[w];
            unsigned run = base;
#pragma unroll
            for (int k = 0; k < 16; k++) {
                g_binpack[b][tid * 16 + k] = run | (c[k] << 16);
                cursor[tid * 16 + k] = run;
                run += c[k];
            }
            __syncthreads();
            for (int i = tid; i < NV; i += 256) {
                float2 v = vb[i];
                int ix = min(63, (int)v.x), iy = min(63, (int)v.y);
                unsigned slot = atomicAdd(&cursor[iy * 64 + ix], 1u);
                g_vsort[b][slot] = v;
            }
        }
        // ============ barrier among the 64 pixel blocks (monotonic) ============
        __syncthreads();
        if (tid == 0) {
            __threadfence();
            unsigned t = atomicAdd(&g_barrier, 1u);
            unsigned target = t - (t % (unsigned)NB_PIX) + (unsigned)NB_PIX;
            while (*(volatile unsigned*)&g_barrier < target) { __nanosleep(32); }
        }
        __syncthreads();

        // ============ stage batch tables into smem ============
        const int b = bx >> 4;
        unsigned* sbin = dyn_u;                       // 4096 words
        float2*   svs  = (float2*)(dyn_u + 4096);     // NV float2
        {
            const int4* s1 = (const int4*)g_binpack[b];
            int4* d1 = (int4*)sbin;
#pragma unroll
            for (int k = 0; k < 4; k++) d1[tid + k * 256] = s1[tid + k * 256];
            const int4* s2 = (const int4*)g_vsort[b];
            int4* d2 = (int4*)svs;
            for (int i = tid; i < (NV * 2) / 4; i += 256) d2[i] = s2[i];  // 3445 int4
        }
        __syncthreads();

        // ============ pixel -> nearest vert (ring search in smem) ============
        const int p = (bx & 15) * 256 + tid;
        if (mask[b * HW + p] > 0) {
            const int cx = p & 63, cy = p >> 6;
            const float px = (float)cx, py = (float)cy;
            float best = INF2;
#define EVAL_VBIN(X, Y) do {                                           \
            unsigned pkd = sbin[(Y) * 64 + (X)];                       \
            int off = pkd & 0xFFFF, n = pkd >> 16;                     \
            for (int k = 0; k < n; k++) {                              \
                float2 w = svs[off + k];                               \
                float dx = px - w.x, dy = py - w.y;                    \
                best = fminf(best, fmaf(dx, dx, dy * dy));             \
            } } while (0)
            for (int r = 0; r <= 63; r++) {
                if (r > 0 && best <= (float)((r - 1) * (r - 1))) break;
                int x0 = max(cx - r, 0), x1 = min(cx + r, 63);
                int yt = cy - r;
                if (yt >= 0) for (int x = x0; x <= x1; x++) EVAL_VBIN(x, yt);
                if (r > 0) {
                    int yb = cy + r;
                    if (yb <= 63) for (int x = x0; x <= x1; x++) EVAL_VBIN(x, yb);
                    int yy0 = max(cy - r + 1, 0), yy1 = min(cy + r - 1, 63);
                    int xl = cx - r, xr = cx + r;
                    if (xl >= 0) for (int y = yy0; y <= yy1; y++) EVAL_VBIN(xl, y);
                    if (xr <= 63) for (int y = yy0; y <= yy1; y++) EVAL_VBIN(xr, y);
                }
            }
            s = sqrt_ap(best) * INV64;
        }
    } else {
        // ================== vert -> nearest valid pixel ==================
        const int g0 = (bx - NB_PIX) * 256;
        const int b_lo = g0 / NV;
        const int b_hi = min((g0 + 255) / NV, BATCH - 1);
        unsigned* sb = dyn_u;    // up to 2*128 bitset words

        for (int bi = 0; bi <= b_hi - b_lo; bi++) {
            const int* mbase = mask + (b_lo + bi) * HW;
#pragma unroll
            for (int it = 0; it < 16; it++) {
                int wl = it * 8 + wid;                       // word 0..127
                int val = mbase[wl * 32 + lane] > 0;
                unsigned word = __ballot_sync(0xffffffffu, val);
                if (lane == 0) sb[bi * 128 + wl] = word;
            }
        }
        __syncthreads();

        const int g = g0 + tid;
        if (g < BATCH * NV) {
            const int b = g / NV;
            float2 v = ((const float2*)vert)[g];
            const float vx = v.x, vy = v.y;
            const int xc = min(63, (int)vx), cy = min(63, (int)vy);
            const unsigned* mb = &sb[(b - b_lo) * 128];
            // bits 0..xc inclusive (left candidates, includes the vert's own column)
            const unsigned long long lmask =
                (xc >= 63) ? ~0ull : ((1ull << (xc + 1)) - 1ull);
            float best = INF2;

            // Correct per-row minimum via two MONOTONE candidate sets:
            //  - highest set bit <= xc   (dist = vx - x >= 0, decreasing toward xc)
            //  - lowest  set bit >= xc+1 (dist = x - vx > 0, increasing with x)
            // ((m >> xc) >> 1) avoids the modular-shift trap at xc == 63.
#define ROW_EVAL(Y, DY) do {                                                     \
            unsigned long long m = (unsigned long long)mb[2 * (Y)] |             \
                                   ((unsigned long long)mb[2 * (Y) + 1] << 32);  \
            if (m) {                                                             \
                float dy2 = (DY) * (DY);                                         \
                unsigned long long ml = m & lmask;                               \
                if (ml) {                                                        \
                    float dx = vx - (float)(63 - __clzll((long long)ml));        \
                    best = fminf(best, fmaf(dx, dx, dy2));                       \
                }                                                                \
                unsigned long long mr = (m >> xc) >> 1;                          \
                if (mr) {                                                        \
                    float dx = (float)(xc + __ffsll((long long)mr)) - vx;        \
                    best = fminf(best, fmaf(dx, dx, dy2));                       \
                }                                                                \
            } } while (0)

            for (int d = 0; d < 64; d++) {
                if (d > 0 && best <= (float)((d - 1) * (d - 1))) break;
                int yd = cy + d;
                if (yd < 64) { float dy = vy - (float)yd; if (dy * dy < best) ROW_EVAL(yd, dy); }
                if (d > 0) {
                    int yu = cy - d;
                    if (yu >= 0) { float dy = vy - (float)yu; if (dy * dy < best) ROW_EVAL(yu, dy); }
                }
            }
            s = (best >= 1.0e17f) ? BIGF : sqrt_ap(best) * INV64;
        }
    }

    // ============ block reduce -> partial; last block sums all ============
    __syncthreads();
    red[tid] = s;
    __syncthreads();
#pragma unroll
    for (int d = 128; d > 0; d >>= 1) {
        if (tid < d) red[tid] += red[tid + d];
        __syncthreads();
    }
    if (tid == 0) {
        g_partial[bx] = red[0];
        __threadfence();
        unsigned t = atomicAdd(&g_ticket, 1u);
        lastflag = ((t % (unsigned)NBLK) == (unsigned)(NBLK - 1));
    }
    __syncthreads();
    if (lastflag) {
        __threadfence();
        float v = (tid < NBLK) ? *(volatile float*)&g_partial[tid] : 0.0f;
        red[tid] = v;
        __syncthreads();
#pragma unroll
        for (int d = 128; d > 0; d >>= 1) {
            if (tid < d) red[tid] += red[tid + d];
            __syncthreads();
        }
        if (tid == 0) out[0] = red[0];
    }
}

extern "C" void kernel_launch(void* const* d_in, const int* in_sizes, int n_in,
                              void* d_out, int out_size) {
    const float* vert2d = (const float*)d_in[0];   // [B, N, 2] float32 (pixel units)
    const int*   mask   = (const int*)d_in[1];     // [B, H, W] int32
    float* out = (float*)d_out;
    (void)in_sizes; (void)n_in; (void)out_size;

    static int configured = 0;
    if (!configured) {
        cudaFuncSetAttribute(k_fused, cudaFuncAttributeMaxDynamicSharedMemorySize, SMEM_BYTES);
        configured = 1;
    }
    k_fused<<<NBLK, 256, SMEM_BYTES>>>(vert2d, mask, out);
}

// round 9
// speedup vs baseline: 1.4484x; 1.4484x over previous
#include <cuda_runtime.h>
#include <math.h>

// MaskAlignmentLoss: single fused kernel, fully decentralized.
// Pixel blocks: per-tile local vert binning in smem + exact ring search.
// Vert blocks: mask bitset via ballot + exact per-row scan.
// B=4, N=6890, H=W=64. Pixel units; scale 1/64 per term.

#define BATCH   4
#define NV      6890
#define HW      4096
#define INF2    1.0e18f
#define INV64   0.015625f
#define BIGF    1.0e9f
#define NB_PIX  64                  // 16 tiles x 4 batches
#define NB_VERT 108                 // 27648 >= 27560 verts
#define NBLK    (NB_PIX + NB_VERT)  // 172
#define RB      4                   // margin (bins/px) around tile
#define REG     24                  // region width = 16 + 2*RB
#define NBIN    (REG * REG)         // 576
#define SMEM_BYTES (NBIN * 4 * 2 + NV * 8)   // 59728

// -------- persistent device state (monotonic; no init across replays) --------
__device__ float    g_partial[NBLK];
__device__ unsigned g_ticket;

__device__ __forceinline__ float sqrt_ap(float x) {
    float r; asm("sqrt.approx.f32 %0, %1;" : "=f"(r) : "f"(x)); return r;
}

extern __shared__ __align__(16) unsigned dyn_u[];

__global__ void __launch_bounds__(256) k_fused(const float* __restrict__ vert,
                                               const int*   __restrict__ mask,
                                               float*       __restrict__ out) {
    __shared__ float red[256];
    __shared__ unsigned wtot[8];
    __shared__ int lastflag;

    const int bx = blockIdx.x, tid = threadIdx.x;
    const int lane = tid & 31, wid = tid >> 5;
    float s = 0.0f;

    if (bx < NB_PIX) {
        // ============== pixel -> nearest vert, one 16x16 tile per block ==============
        const int b  = bx >> 4;
        const int t  = bx & 15;
        const int ox = (t & 3) * 16, oy = (t >> 2) * 16;   // tile origin
        const int rx0 = ox - RB, ry0 = oy - RB;            // region origin

        unsigned* scnt  = dyn_u;                   // [NBIN] counts -> cursors
        unsigned* sdesc = dyn_u + NBIN;            // [NBIN] off | (cnt<<16)
        float2*   svs   = (float2*)(dyn_u + 2 * NBIN);   // [<=NV]

        // zero counts
        scnt[tid] = 0; scnt[tid + 256] = 0;
        if (tid < NBIN - 512) scnt[tid + 512] = 0;
        __syncthreads();

        // pass 1: count in-region verts
        const float2* vb = (const float2*)(vert + (size_t)b * NV * 2);
        for (int i = tid; i < NV; i += 256) {
            float2 v = vb[i];
            int lx = min(63, (int)v.x) - rx0;
            int ly = min(63, (int)v.y) - ry0;
            if ((unsigned)lx < REG && (unsigned)ly < REG)
                atomicAdd(&scnt[ly * REG + lx], 1u);
        }
        __syncthreads();

        // block scan over NBIN counts (thread owns bins tid, tid+256, tid+512)
        {
            unsigned c0 = scnt[tid];
            unsigned c1 = scnt[tid + 256];
            unsigned c2 = (tid < NBIN - 512) ? scnt[tid + 512] : 0;
            unsigned tsum = c0 + c1 + c2;
            unsigned incl = tsum;
#pragma unroll
            for (int d = 1; d < 32; d <<= 1) {
                unsigned u = __shfl_up_sync(0xffffffffu, incl, d);
                if (lane >= d) incl += u;
            }
            if (lane == 31) wtot[wid] = incl;
            __syncthreads();
            unsigned base = incl - tsum;
            for (int w = 0; w < wid; w++) base += wtot[w];
            // disjoint ranges per bin (ordering across bins irrelevant)
            sdesc[tid] = base | (c0 << 16);          scnt[tid] = base;        base += c0;
            sdesc[tid + 256] = base | (c1 << 16);    scnt[tid + 256] = base;  base += c1;
            if (tid < NBIN - 512) {
                sdesc[tid + 512] = base | (c2 << 16); scnt[tid + 512] = base;
            }
        }
        __syncthreads();

        // pass 2: scatter in-region verts to smem (gmem re-read hits L2)
        for (int i = tid; i < NV; i += 256) {
            float2 v = vb[i];
            int lx = min(63, (int)v.x) - rx0;
            int ly = min(63, (int)v.y) - ry0;
            if ((unsigned)lx < REG && (unsigned)ly < REG) {
                unsigned slot = atomicAdd(&scnt[ly * REG + lx], 1u);
                svs[slot] = v;
            }
        }
        __syncthreads();

        // ring search (exact; rings 0..RB stay inside the region by construction)
        const int cx = ox + (tid & 15), cy = oy + (tid >> 4);
        if (mask[b * HW + cy * 64 + cx] > 0) {
            const float px = (float)cx, py = (float)cy;
            float best = INF2;
#define EVAL_VBIN(X, Y) do {                                              \
            unsigned pkd = sdesc[((Y) - ry0) * REG + ((X) - rx0)];        \
            int off = pkd & 0xFFFF, n = pkd >> 16;                        \
            for (int k = 0; k < n; k++) {                                 \
                float2 w = svs[off + k];                                  \
                float dx = px - w.x, dy = py - w.y;                       \
                best = fminf(best, fmaf(dx, dx, dy * dy));                \
            } } while (0)
            for (int r = 0; r <= RB; r++) {
                if (r > 0 && best <= (float)((r - 1) * (r - 1))) break;
                int x0 = max(cx - r, 0), x1 = min(cx + r, 63);
                int yt = cy - r;
                if (yt >= 0) for (int x = x0; x <= x1; x++) EVAL_VBIN(x, yt);
                if (r > 0) {
                    int yb = cy + r;
                    if (yb <= 63) for (int x = x0; x <= x1; x++) EVAL_VBIN(x, yb);
                    int yy0 = max(cy - r + 1, 0), yy1 = min(cy + r - 1, 63);
                    int xl = cx - r, xr = cx + r;
                    if (xl >= 0)  for (int y = yy0; y <= yy1; y++) EVAL_VBIN(xl, y);
                    if (xr <= 63) for (int y = yy0; y <= yy1; y++) EVAL_VBIN(xr, y);
                }
            }
            // exactness guard: verts outside region have d > RB -> d^2 > RB^2
            if (!(best <= (float)(RB * RB))) {
                for (int i = 0; i < NV; i++) {
                    float2 w = vb[i];
                    float dx = px - w.x, dy = py - w.y;
                    best = fminf(best, fmaf(dx, dx, dy * dy));
                }
            }
            s = sqrt_ap(best) * INV64;
        }
    } else {
        // ================== vert -> nearest valid pixel ==================
        const int g0 = (bx - NB_PIX) * 256;
        const int b_lo = g0 / NV;
        const int b_hi = min((g0 + 255) / NV, BATCH - 1);
        unsigned* sb = dyn_u;    // up to 2*128 bitset words

        for (int bi = 0; bi <= b_hi - b_lo; bi++) {
            const int* mbase = mask + (b_lo + bi) * HW;
#pragma unroll
            for (int it = 0; it < 16; it++) {
                int wl = it * 8 + wid;                       // word 0..127
                int val = mbase[wl * 32 + lane] > 0;
                unsigned word = __ballot_sync(0xffffffffu, val);
                if (lane == 0) sb[bi * 128 + wl] = word;
            }
        }
        __syncthreads();

        const int g = g0 + tid;
        if (g < BATCH * NV) {
            const int b = g / NV;
            float2 v = ((const float2*)vert)[g];
            const float vx = v.x, vy = v.y;
            const int xc = min(63, (int)vx), cy = min(63, (int)vy);
            const unsigned* mb = &sb[(b - b_lo) * 128];
            const unsigned long long lmask =
                (xc >= 63) ? ~0ull : ((1ull << (xc + 1)) - 1ull);
            float best = INF2;

            // per-row exact minimum via two monotone candidate sets:
            //  highest set bit <= xc, lowest set bit >= xc+1
#define ROW_EVAL(Y, DY) do {                                                     \
            unsigned long long m = (unsigned long long)mb[2 * (Y)] |             \
                                   ((unsigned long long)mb[2 * (Y) + 1] << 32);  \
            if (m) {                                                             \
                float dy2 = (DY) * (DY);                                         \
                unsigned long long ml = m & lmask;                               \
                if (ml) {                                                        \
                    float dx = vx - (float)(63 - __clzll((long long)ml));        \
                    best = fminf(best, fmaf(dx, dx, dy2));                       \
                }                                                                \
                unsigned long long mr = (m >> xc) >> 1;                          \
                if (mr) {                                                        \
                    float dx = (float)(xc + __ffsll((long long)mr)) - vx;        \
                    best = fminf(best, fmaf(dx, dx, dy2));                       \
                }                                                                \
            } } while (0)

            for (int d = 0; d < 64; d++) {
                if (d > 0 && best <= (float)((d - 1) * (d - 1))) break;
                int yd = cy + d;
                if (yd < 64) { float dy = vy - (float)yd; if (dy * dy < best) ROW_EVAL(yd, dy); }
                if (d > 0) {
                    int yu = cy - d;
                    if (yu >= 0) { float dy = vy - (float)yu; if (dy * dy < best) ROW_EVAL(yu, dy); }
                }
            }
            s = (best >= 1.0e17f) ? BIGF : sqrt_ap(best) * INV64;
        }
    }

    // ============ block reduce -> partial; last finisher sums all ============
    __syncthreads();
    red[tid] = s;
    __syncthreads();
#pragma unroll
    for (int d = 128; d > 0; d >>= 1) {
        if (tid < d) red[tid] += red[tid + d];
        __syncthreads();
    }
    if (tid == 0) {
        g_partial[bx] = red[0];
        __threadfence();
        unsigned t = atomicAdd(&g_ticket, 1u);
        lastflag = ((t % (unsigned)NBLK) == (unsigned)(NBLK - 1));
    }
    __syncthreads();
    if (lastflag) {
        __threadfence();
        float v = (tid < NBLK) ? *(volatile float*)&g_partial[tid] : 0.0f;
        red[tid] = v;
        __syncthreads();
#pragma unroll
        for (int d = 128; d > 0; d >>= 1) {
            if (tid < d) red[tid] += red[tid + d];
            __syncthreads();
        }
        if (tid == 0) out[0] = red[0];
    }
}

extern "C" void kernel_launch(void* const* d_in, const int* in_sizes, int n_in,
                              void* d_out, int out_size) {
    const float* vert2d = (const float*)d_in[0];   // [B, N, 2] float32 (pixel units)
    const int*   mask   = (const int*)d_in[1];     // [B, H, W] int32
    float* out = (float*)d_out;
    (void)in_sizes; (void)n_in; (void)out_size;

    static int configured = 0;
    if (!configured) {
        cudaFuncSetAttribute(k_fused, cudaFuncAttributeMaxDynamicSharedMemorySize, SMEM_BYTES);
        configured = 1;
    }
    k_fused<<<NBLK, 256, SMEM_BYTES>>>(vert2d, mask, out);
}

// round 10
// speedup vs baseline: 1.8488x; 1.2765x over previous
#include <cuda_runtime.h>
#include <math.h>

// MaskAlignmentLoss: single fused kernel, decentralized, single-pass binning.
// Pixel blocks: per-tile capacity-8 bins in smem (1 vert scan) + exact ring search.
// Vert blocks: mask bitset via ballot + exact per-row scan.
// B=4, N=6890, H=W=64. Pixel units; scale 1/64 per term.

#define BATCH   4
#define NV      6890
#define HW      4096
#define INF2    1.0e18f
#define INV64   0.015625f
#define BIGF    1.0e9f
#define NB_PIX  64                  // 16 tiles x 4 batches
#define NB_VERT 108                 // 27648 >= 27560 verts
#define NBLK    (NB_PIX + NB_VERT)  // 172
#define RB      4                   // ring margin (px)
#define REG     24                  // region width = 16 + 2*RB
#define NBIN    (REG * REG)         // 576
#define CAP     8                   // slots per bin
#define OVF_CAP 64
#define SMEM_BYTES (NBIN * 4 + NBIN * CAP * 8 + OVF_CAP * 8)   // 39680

// -------- persistent device state (monotonic; no init across replays) --------
__device__ float    g_partial[NBLK];
__device__ unsigned g_ticket;

__device__ __forceinline__ float sqrt_ap(float x) {
    float r; asm("sqrt.approx.f32 %0, %1;" : "=f"(r) : "f"(x)); return r;
}

extern __shared__ __align__(16) unsigned dyn_u[];

__global__ void __launch_bounds__(256) k_fused(const float* __restrict__ vert,
                                               const int*   __restrict__ mask,
                                               float*       __restrict__ out) {
    __shared__ float red[256];
    __shared__ unsigned s_ovf_cnt;
    __shared__ int s_fallback;
    __shared__ int lastflag;

    const int bx = blockIdx.x, tid = threadIdx.x;
    const int lane = tid & 31, wid = tid >> 5;
    float s = 0.0f;

    if (bx < NB_PIX) {
        // ============ pixel -> nearest vert, one 16x16 tile per block ============
        const int b  = bx >> 4;
        const int t  = bx & 15;
        const int ox = (t & 3) * 16, oy = (t >> 2) * 16;   // tile origin
        const int rx0 = ox - RB, ry0 = oy - RB;            // region origin
        const int cx = ox + (tid & 15), cy = oy + (tid >> 4);

        unsigned* scnt = dyn_u;                                  // [NBIN]
        float2*   sbin = (float2*)(dyn_u + NBIN);                // [NBIN*CAP]
        float2*   sovf = (float2*)(dyn_u + NBIN + NBIN * CAP * 2); // [OVF_CAP]

        // early independent load: own mask value (overlaps with binning)
        const int mymask = mask[b * HW + cy * 64 + cx];

        // zero bin counts (576 words over 256 threads)
        scnt[tid] = 0; scnt[tid + 256] = 0;
        if (tid < NBIN - 512) scnt[tid + 512] = 0;
        if (tid == 0) { s_ovf_cnt = 0; s_fallback = 0; }
        __syncthreads();

        // single-pass binning: float4 loads (2 verts / element), direct append
        const float2* vb  = (const float2*)(vert + (size_t)b * NV * 2);
        const float4* vb4 = (const float4*)vb;               // NV even -> 3445
        for (int i = tid; i < NV / 2; i += 256) {
            float4 q = vb4[i];
#pragma unroll
            for (int h = 0; h < 2; h++) {
                float vx = h ? q.z : q.x, vy = h ? q.w : q.y;
                int lx = min(63, (int)vx) - rx0;
                int ly = min(63, (int)vy) - ry0;
                if ((unsigned)lx < REG && (unsigned)ly < REG) {
                    int bin = ly * REG + lx;
                    unsigned slot = atomicAdd(&scnt[bin], 1u);
                    if (slot < CAP) {
                        sbin[bin * CAP + slot] = make_float2(vx, vy);
                    } else {
                        unsigned o = atomicAdd(&s_ovf_cnt, 1u);
                        if (o < OVF_CAP) sovf[o] = make_float2(vx, vy);
                        else s_fallback = 1;
                    }
                }
            }
        }
        __syncthreads();

        if (mymask > 0) {
            const float px = (float)cx, py = (float)cy;
            float best = INF2;
#define EVAL_VBIN(X, Y) do {                                               \
            int bin = ((Y) - ry0) * REG + ((X) - rx0);                     \
            int n = min(scnt[bin], (unsigned)CAP);                         \
            for (int k = 0; k < n; k++) {                                  \
                float2 w = sbin[bin * CAP + k];                            \
                float dx = px - w.x, dy = py - w.y;                        \
                best = fminf(best, fmaf(dx, dx, dy * dy));                 \
            } } while (0)
            for (int r = 0; r <= RB; r++) {
                if (r > 0 && best <= (float)((r - 1) * (r - 1))) break;
                int x0 = max(cx - r, 0), x1 = min(cx + r, 63);
                int yt = cy - r;
                if (yt >= 0) for (int x = x0; x <= x1; x++) EVAL_VBIN(x, yt);
                if (r > 0) {
                    int yb = cy + r;
                    if (yb <= 63) for (int x = x0; x <= x1; x++) EVAL_VBIN(x, yb);
                    int yy0 = max(cy - r + 1, 0), yy1 = min(cy + r - 1, 63);
                    int xl = cx - r, xr = cx + r;
                    if (xl >= 0)  for (int y = yy0; y <= yy1; y++) EVAL_VBIN(xl, y);
                    if (xr <= 63) for (int y = yy0; y <= yy1; y++) EVAL_VBIN(xr, y);
                }
            }
            // overflow list: real verts -> true distances; scanning extra
            // candidates can never push best below the true NN distance.
            int no = min(s_ovf_cnt, (unsigned)OVF_CAP);
            for (int k = 0; k < no; k++) {
                float2 w = sovf[k];
                float dx = px - w.x, dy = py - w.y;
                best = fminf(best, fmaf(dx, dx, dy * dy));
            }
            // exactness guards: region miss (best > RB^2) or list overflow
            if (s_fallback || !(best <= (float)(RB * RB))) {
                for (int i = 0; i < NV; i++) {
                    float2 w = vb[i];
                    float dx = px - w.x, dy = py - w.y;
                    best = fminf(best, fmaf(dx, dx, dy * dy));
                }
            }
            s = sqrt_ap(best) * INV64;
        }
    } else {
        // ================== vert -> nearest valid pixel ==================
        const int g0 = (bx - NB_PIX) * 256;
        const int b_lo = g0 / NV;
        const int b_hi = min((g0 + 255) / NV, BATCH - 1);
        unsigned* sb = dyn_u;    // up to 2*128 bitset words

        for (int bi = 0; bi <= b_hi - b_lo; bi++) {
            const int* mbase = mask + (b_lo + bi) * HW;
#pragma unroll
            for (int it = 0; it < 16; it++) {
                int wl = it * 8 + wid;                       // word 0..127
                int val = mbase[wl * 32 + lane] > 0;
                unsigned word = __ballot_sync(0xffffffffu, val);
                if (lane == 0) sb[bi * 128 + wl] = word;
            }
        }
        __syncthreads();

        const int g = g0 + tid;
        if (g < BATCH * NV) {
            const int b = g / NV;
            float2 v = ((const float2*)vert)[g];
            const float vx = v.x, vy = v.y;
            const int xc = min(63, (int)vx), cy = min(63, (int)vy);
            const unsigned* mb = &sb[(b - b_lo) * 128];
            const unsigned long long lmask =
                (xc >= 63) ? ~0ull : ((1ull << (xc + 1)) - 1ull);
            float best = INF2;

            // exact per-row minimum via two monotone candidate sets:
            //  highest set bit <= xc, lowest set bit >= xc+1
#define ROW_EVAL(Y, DY) do {                                                     \
            unsigned long long m = (unsigned long long)mb[2 * (Y)] |             \
                                   ((unsigned long long)mb[2 * (Y) + 1] << 32);  \
            if (m) {                                                             \
                float dy2 = (DY) * (DY);                                         \
                unsigned long long ml = m & lmask;                               \
                if (ml) {                                                        \
                    float dx = vx - (float)(63 - __clzll((long long)ml));        \
                    best = fminf(best, fmaf(dx, dx, dy2));                       \
                }                                                                \
                unsigned long long mr = (m >> xc) >> 1;                          \
                if (mr) {                                                        \
                    float dx = (float)(xc + __ffsll((long long)mr)) - vx;        \
                    best = fminf(best, fmaf(dx, dx, dy2));                       \
                }                                                                \
            } } while (0)

            for (int d = 0; d < 64; d++) {
                if (d > 0 && best <= (float)((d - 1) * (d - 1))) break;
                int yd = cy + d;
                if (yd < 64) { float dy = vy - (float)yd; if (dy * dy < best) ROW_EVAL(yd, dy); }
                if (d > 0) {
                    int yu = cy - d;
                    if (yu >= 0) { float dy = vy - (float)yu; if (dy * dy < best) ROW_EVAL(yu, dy); }
                }
            }
            s = (best >= 1.0e17f) ? BIGF : sqrt_ap(best) * INV64;
        }
    }

    // ============ block reduce -> partial; last finisher sums all ============
    __syncthreads();
    red[tid] = s;
    __syncthreads();
#pragma unroll
    for (int d = 128; d > 0; d >>= 1) {
        if (tid < d) red[tid] += red[tid + d];
        __syncthreads();
    }
    if (tid == 0) {
        g_partial[bx] = red[0];
        __threadfence();
        unsigned t = atomicAdd(&g_ticket, 1u);
        lastflag = ((t % (unsigned)NBLK) == (unsigned)(NBLK - 1));
    }
    __syncthreads();
    if (lastflag) {
        __threadfence();
        float v = (tid < NBLK) ? *(volatile float*)&g_partial[tid] : 0.0f;
        red[tid] = v;
        __syncthreads();
#pragma unroll
        for (int d = 128; d > 0; d >>= 1) {
            if (tid < d) red[tid] += red[tid + d];
            __syncthreads();
        }
        if (tid == 0) out[0] = red[0];
    }
}

extern "C" void kernel_launch(void* const* d_in, const int* in_sizes, int n_in,
                              void* d_out, int out_size) {
    const float* vert2d = (const float*)d_in[0];   // [B, N, 2] float32 (pixel units)
    const int*   mask   = (const int*)d_in[1];     // [B, H, W] int32
    float* out = (float*)d_out;
    (void)in_sizes; (void)n_in; (void)out_size;

    static int configured = 0;
    if (!configured) {
        cudaFuncSetAttribute(k_fused, cudaFuncAttributeMaxDynamicSharedMemorySize, SMEM_BYTES);
        configured = 1;
    }
    k_fused<<<NBLK, 256, SMEM_BYTES>>>(vert2d, mask, out);
}